// round 16
// baseline (speedup 1.0000x reference)
#include <cuda_runtime.h>
#include <cuda_fp16.h>
#include <math.h>
#include <stdint.h>

#define NMAX 50176
#define EMAX 800000

// ---------------- scratch (device globals; zero-initialized at module load) ----
__device__ float  g_h  [NMAX * 128];
__device__ __half g_xlh[NMAX * 256];
__device__ __half g_xrh[NMAX * 256];
__device__ float  g_h1 [NMAX * 64];
__device__ int    g_cnt   [NMAX];    // self-zeroed by gat layer-2 each run
__device__ int    g_rowptr[NMAX];
__device__ int    g_woff  [NMAX];
__device__ int    g_part  [256];
__device__ int    g_csrsrc[EMAX];

__device__ __forceinline__ float eluf(float x) { return x > 0.f ? x : expm1f(x); }

// ================= GEMM body: 128x128 tile, BK=16, FFMA2 =======================
__device__ __forceinline__ void gemm_body(
    const float* __restrict__ A, const float* __restrict__ W,
    const float* __restrict__ bias, float* __restrict__ C, __half* __restrict__ Ch,
    int M, int K, int Nc, int rowBase, int colBase,
    const float* __restrict__ lnw, const float* __restrict__ lnb)
{
    __shared__ float As[2][16][128];
    __shared__ float Bs[2][16][128];

    const int tid = threadIdx.x;
    const int tx = tid & 15;
    const int ty = tid >> 4;

    const int lr = tid & 127;
    const int lc = (tid >> 7) * 4;
    const int wk = tid >> 5;
    const int wc = (tid & 31) * 4;

    const bool aok = (rowBase + lr) < M;
    const float* Arow = A + (size_t)(rowBase + lr) * K;
    const float* Wp = W + colBase + wc;

    const float4 z4 = make_float4(0.f, 0.f, 0.f, 0.f);
    float4 av0 = aok ? *(const float4*)(Arow + lc)     : z4;
    float4 av1 = aok ? *(const float4*)(Arow + lc + 8) : z4;
    float4 bv0 = *(const float4*)(Wp + (size_t)wk * Nc);
    float4 bv1 = *(const float4*)(Wp + (size_t)(wk + 8) * Nc);

    As[0][lc + 0][lr] = av0.x; As[0][lc + 1][lr] = av0.y;
    As[0][lc + 2][lr] = av0.z; As[0][lc + 3][lr] = av0.w;
    As[0][lc + 8][lr] = av1.x; As[0][lc + 9][lr] = av1.y;
    As[0][lc +10][lr] = av1.z; As[0][lc +11][lr] = av1.w;
    *(float4*)&Bs[0][wk][wc]     = bv0;
    *(float4*)&Bs[0][wk + 8][wc] = bv1;
    __syncthreads();

    unsigned long long acc2[8][4];
    #pragma unroll
    for (int i = 0; i < 8; i++)
        #pragma unroll
        for (int j = 0; j < 4; j++) acc2[i][j] = 0ULL;

    const int T = K >> 4;
    for (int t = 0; t < T; t++) {
        const int buf = t & 1;
        if (t + 1 < T) {
            const int k0 = (t + 1) << 4;
            av0 = aok ? *(const float4*)(Arow + k0 + lc)     : z4;
            av1 = aok ? *(const float4*)(Arow + k0 + lc + 8) : z4;
            bv0 = *(const float4*)(Wp + (size_t)(k0 + wk) * Nc);
            bv1 = *(const float4*)(Wp + (size_t)(k0 + wk + 8) * Nc);
        }
        #pragma unroll
        for (int kk = 0; kk < 16; kk++) {
            float a[8];
            *(float4*)&a[0] = *(const float4*)&As[buf][kk][ty * 8];
            *(float4*)&a[4] = *(const float4*)&As[buf][kk][ty * 8 + 4];
            ulonglong2 q0 = *(const ulonglong2*)&Bs[buf][kk][tx * 8];
            ulonglong2 q1 = *(const ulonglong2*)&Bs[buf][kk][tx * 8 + 4];
            unsigned long long bp[4] = { q0.x, q0.y, q1.x, q1.y };
            #pragma unroll
            for (int i = 0; i < 8; i++) {
                unsigned long long ad;
                asm("mov.b64 %0, {%1,%1};" : "=l"(ad) : "f"(a[i]));
                #pragma unroll
                for (int j = 0; j < 4; j++)
                    asm("fma.rn.f32x2 %0, %1, %2, %0;"
                        : "+l"(acc2[i][j]) : "l"(ad), "l"(bp[j]));
            }
        }
        if (t + 1 < T) {
            const int nb = buf ^ 1;
            As[nb][lc + 0][lr] = av0.x; As[nb][lc + 1][lr] = av0.y;
            As[nb][lc + 2][lr] = av0.z; As[nb][lc + 3][lr] = av0.w;
            As[nb][lc + 8][lr] = av1.x; As[nb][lc + 9][lr] = av1.y;
            As[nb][lc +10][lr] = av1.z; As[nb][lc +11][lr] = av1.w;
            *(float4*)&Bs[nb][wk][wc]     = bv0;
            *(float4*)&Bs[nb][wk + 8][wc] = bv1;
            __syncthreads();
        }
    }

    const int cbase = colBase + tx * 8;
    float4 b0 = *(const float4*)(bias + cbase);
    float4 b1 = *(const float4*)(bias + cbase + 4);

    if (Ch != nullptr) {
        #pragma unroll
        for (int i = 0; i < 8; i++) {
            int r = rowBase + ty * 8 + i;
            if (r >= M) continue;
            float c[8];
            #pragma unroll
            for (int j = 0; j < 4; j++)
                asm("mov.b64 {%0,%1}, %2;" : "=f"(c[2*j]), "=f"(c[2*j+1]) : "l"(acc2[i][j]));
            __half2 hh[4];
            hh[0] = __floats2half2_rn(c[0] + b0.x, c[1] + b0.y);
            hh[1] = __floats2half2_rn(c[2] + b0.z, c[3] + b0.w);
            hh[2] = __floats2half2_rn(c[4] + b1.x, c[5] + b1.y);
            hh[3] = __floats2half2_rn(c[6] + b1.z, c[7] + b1.w);
            *(uint4*)(Ch + (size_t)r * Nc + cbase) = *(uint4*)hh;
        }
    } else if (lnw == nullptr) {
        #pragma unroll
        for (int i = 0; i < 8; i++) {
            int r = rowBase + ty * 8 + i;
            if (r >= M) continue;
            float c[8];
            #pragma unroll
            for (int j = 0; j < 4; j++)
                asm("mov.b64 {%0,%1}, %2;" : "=f"(c[2*j]), "=f"(c[2*j+1]) : "l"(acc2[i][j]));
            float4 o0 = make_float4(c[0] + b0.x, c[1] + b0.y, c[2] + b0.z, c[3] + b0.w);
            float4 o1 = make_float4(c[4] + b1.x, c[5] + b1.y, c[6] + b1.z, c[7] + b1.w);
            *(float4*)(C + (size_t)r * Nc + cbase)     = o0;
            *(float4*)(C + (size_t)r * Nc + cbase + 4) = o1;
        }
    } else {
        float s[8], sq[8];
        #pragma unroll
        for (int i = 0; i < 8; i++) {
            float c[8];
            #pragma unroll
            for (int j = 0; j < 4; j++)
                asm("mov.b64 {%0,%1}, %2;" : "=f"(c[2*j]), "=f"(c[2*j+1]) : "l"(acc2[i][j]));
            c[0] += b0.x; c[1] += b0.y; c[2] += b0.z; c[3] += b0.w;
            c[4] += b1.x; c[5] += b1.y; c[6] += b1.z; c[7] += b1.w;
            float ss = 0.f, qq = 0.f;
            #pragma unroll
            for (int j = 0; j < 8; j++) { ss += c[j]; qq += c[j] * c[j]; }
            s[i] = ss; sq[i] = qq;
        }
        #pragma unroll
        for (int o = 1; o < 16; o <<= 1) {
            #pragma unroll
            for (int i = 0; i < 8; i++) {
                s[i]  += __shfl_xor_sync(0xffffffffu, s[i],  o);
                sq[i] += __shfl_xor_sync(0xffffffffu, sq[i], o);
            }
        }
        float4 lw0 = *(const float4*)(lnw + cbase);
        float4 lw1 = *(const float4*)(lnw + cbase + 4);
        float4 lb0 = *(const float4*)(lnb + cbase);
        float4 lb1 = *(const float4*)(lnb + cbase + 4);
        #pragma unroll
        for (int i = 0; i < 8; i++) {
            int r = rowBase + ty * 8 + i;
            if (r >= M) continue;
            float mean = s[i] * (1.f / 128.f);
            float var  = sq[i] * (1.f / 128.f) - mean * mean;
            float inv  = rsqrtf(var + 1e-5f);
            float c[8];
            #pragma unroll
            for (int j = 0; j < 4; j++)
                asm("mov.b64 {%0,%1}, %2;" : "=f"(c[2*j]), "=f"(c[2*j+1]) : "l"(acc2[i][j]));
            c[0] += b0.x; c[1] += b0.y; c[2] += b0.z; c[3] += b0.w;
            c[4] += b1.x; c[5] += b1.y; c[6] += b1.z; c[7] += b1.w;
            float4 o0, o1;
            o0.x = eluf((c[0] - mean) * inv * lw0.x + lb0.x);
            o0.y = eluf((c[1] - mean) * inv * lw0.y + lb0.y);
            o0.z = eluf((c[2] - mean) * inv * lw0.z + lb0.z);
            o0.w = eluf((c[3] - mean) * inv * lw0.w + lb0.w);
            o1.x = eluf((c[4] - mean) * inv * lw1.x + lb1.x);
            o1.y = eluf((c[5] - mean) * inv * lw1.y + lb1.y);
            o1.z = eluf((c[6] - mean) * inv * lw1.z + lb1.z);
            o1.w = eluf((c[7] - mean) * inv * lw1.w + lb1.w);
            *(float4*)(C + (size_t)r * Nc + cbase)     = o0;
            *(float4*)(C + (size_t)r * Nc + cbase + 4) = o1;
        }
    }
}

// ================= CSR small kernels =============================================
__device__ __forceinline__ void scan1_body(const int* __restrict__ cnt,
                                           int* __restrict__ rowptr,
                                           int* __restrict__ part, int N, int b)
{
    __shared__ int sh[256];
    int tid = threadIdx.x;
    int i = b * 256 + tid;
    int v = (i < N) ? cnt[i] : 0;
    sh[tid] = v; __syncthreads();
    #pragma unroll
    for (int o = 1; o < 256; o <<= 1) {
        int t = (tid >= o) ? sh[tid - o] : 0;
        __syncthreads();
        sh[tid] += t;
        __syncthreads();
    }
    if (i < N) rowptr[i] = sh[tid] - v;
    if (tid == 255) part[b] = sh[255];
}
__global__ void scan3f(int* __restrict__ rowptr, const int* __restrict__ part,
                       int* __restrict__ woff, int N, int NB)
{
    __shared__ int sh[256];
    int tid = threadIdx.x;
    int v = (tid < NB) ? part[tid] : 0;
    sh[tid] = v; __syncthreads();
    #pragma unroll
    for (int o = 1; o < 256; o <<= 1) {
        int t = (tid >= o) ? sh[tid - o] : 0;
        __syncthreads();
        sh[tid] += t;
        __syncthreads();
    }
    int i = blockIdx.x * 256 + tid;
    if (i < N) {
        int b = blockIdx.x;
        int off = sh[b] - ((b < NB) ? part[b] : 0);
        int r = rowptr[i] + off;
        rowptr[i] = r;
        woff[i] = r;
    }
}
// 4 independent edge chains per thread (MLP over the 318-cyc ATOMG latency)
__global__ void csr_scatter(const int* __restrict__ src, const int* __restrict__ dst,
                            int* __restrict__ woff, int* __restrict__ csrsrc,
                            int E, int T)
{
    int t = blockIdx.x * blockDim.x + threadIdx.x;
    int e0 = t, e1 = t + T, e2 = t + 2 * T, e3 = t + 3 * T;
    int d0 = 0, d1 = 0, d2 = 0, d3 = 0;
    int s0 = 0, s1 = 0, s2 = 0, s3 = 0;
    if (e0 < E) { d0 = dst[e0]; s0 = src[e0]; }
    if (e1 < E) { d1 = dst[e1]; s1 = src[e1]; }
    if (e2 < E) { d2 = dst[e2]; s2 = src[e2]; }
    if (e3 < E) { d3 = dst[e3]; s3 = src[e3]; }
    int p0 = 0, p1 = 0, p2 = 0, p3 = 0;
    if (e0 < E) p0 = atomicAdd(&woff[d0], 1);
    if (e1 < E) p1 = atomicAdd(&woff[d1], 1);
    if (e2 < E) p2 = atomicAdd(&woff[d2], 1);
    if (e3 < E) p3 = atomicAdd(&woff[d3], 1);
    if (e0 < E) csrsrc[p0] = s0;
    if (e1 < E) csrsrc[p1] = s1;
    if (e2 < E) csrsrc[p2] = s2;
    if (e3 < E) csrsrc[p3] = s3;
}

// ================= FAT kernel 1: stage-0 GEMM (+LN+ELU)  ∥  csr_count(x4) =======
__global__ void __launch_bounds__(256, 2)
fk_gemm0_count(const float* __restrict__ x, const float* __restrict__ W1,
               const float* __restrict__ b1, float* __restrict__ h, int M,
               const float* __restrict__ lnw, const float* __restrict__ lnb,
               const int* __restrict__ dst, int* __restrict__ cnt,
               int E, int T, int rbY)
{
    if ((int)blockIdx.y < rbY) {
        gemm_body(x, W1, b1, h, nullptr, M, 128, 128, blockIdx.y * 128, 0, lnw, lnb);
    } else {
        int t = (blockIdx.y - rbY) * 256 + threadIdx.x;
        int e0 = t, e1 = t + T, e2 = t + 2 * T, e3 = t + 3 * T;
        int d0 = 0, d1 = 0, d2 = 0, d3 = 0;
        if (e0 < E) d0 = dst[e0];
        if (e1 < E) d1 = dst[e1];
        if (e2 < E) d2 = dst[e2];
        if (e3 < E) d3 = dst[e3];
        if (e0 < E) atomicAdd(&cnt[d0], 1);
        if (e1 < E) atomicAdd(&cnt[d1], 1);
        if (e2 < E) atomicAdd(&cnt[d2], 1);
        if (e3 < E) atomicAdd(&cnt[d3], 1);
    }
}

// ================= FAT kernel 2: dual GEMM (fp16 out)  ∥  optional scan1 ========
__global__ void __launch_bounds__(256, 2)
fk_dualgemm_scan(const float* __restrict__ A,
                 const float* __restrict__ Wl, const float* __restrict__ bl,
                 const float* __restrict__ Wr, const float* __restrict__ br,
                 __half* __restrict__ Clh, __half* __restrict__ Crh, int M, int K,
                 const int* __restrict__ cnt, int* __restrict__ rowptr,
                 int* __restrict__ part, int N, int NB, int rbY)
{
    if ((int)blockIdx.y < rbY) {
        const int which = blockIdx.x >> 1;
        const int colBase = (blockIdx.x & 1) * 128;
        gemm_body(A, which ? Wr : Wl, which ? br : bl, nullptr,
                  which ? Crh : Clh, M, K, 256, blockIdx.y * 128, colBase,
                  nullptr, nullptr);
    } else {
        int b = (blockIdx.y - rbY) * 4 + blockIdx.x;
        if (b < NB) scan1_body(cnt, rowptr, part, N, b);
    }
}

// ================= fused node-major GATv2 (2-way ILP, fp16 inputs) ==============
__device__ __forceinline__ float alpha_lane(const float4 a0, const float4 a1,
                                            const float4 r0, const float4 r1,
                                            const float4 w0, const float4 w1)
{
    float t, al = 0.f;
    t = a0.x + r0.x; t = t >= 0.f ? t : 0.2f * t; al += t * w0.x;
    t = a0.y + r0.y; t = t >= 0.f ? t : 0.2f * t; al += t * w0.y;
    t = a0.z + r0.z; t = t >= 0.f ? t : 0.2f * t; al += t * w0.z;
    t = a0.w + r0.w; t = t >= 0.f ? t : 0.2f * t; al += t * w0.w;
    t = a1.x + r1.x; t = t >= 0.f ? t : 0.2f * t; al += t * w1.x;
    t = a1.y + r1.y; t = t >= 0.f ? t : 0.2f * t; al += t * w1.y;
    t = a1.z + r1.z; t = t >= 0.f ? t : 0.2f * t; al += t * w1.z;
    t = a1.w + r1.w; t = t >= 0.f ? t : 0.2f * t; al += t * w1.w;
    return al;
}

__device__ __forceinline__ void h8_to_f8(uint4 v, float4& A, float4& B)
{
    const __half2* hp = (const __half2*)&v;
    float2 f0 = __half22float2(hp[0]);
    float2 f1 = __half22float2(hp[1]);
    float2 f2 = __half22float2(hp[2]);
    float2 f3 = __half22float2(hp[3]);
    A = make_float4(f0.x, f0.y, f1.x, f1.y);
    B = make_float4(f2.x, f2.y, f3.x, f3.y);
}

template<bool HEADS>
__global__ void gat_node_t(const __half* __restrict__ xlh, const __half* __restrict__ xrh,
                           const int* __restrict__ rowptr, int* __restrict__ cnt,
                           const int* __restrict__ csrsrc, const float* __restrict__ att,
                           const float* __restrict__ bias,
                           const float* __restrict__ resid, float* __restrict__ out,
                           const float* __restrict__ Wmu, const float* __restrict__ bmu,
                           const float* __restrict__ Wlv, const float* __restrict__ blv,
                           float* __restrict__ outmu, float* __restrict__ outlv, int N)
{
    __shared__ float sW [HEADS ? 4096 : 1];
    __shared__ float sH2[HEADS ? 512  : 1];

    if (HEADS) {
        for (int i = threadIdx.x; i < 4096; i += blockDim.x)
            sW[i] = (i < 2048) ? Wmu[i] : Wlv[i - 2048];
        __syncthreads();
    }

    int node = (blockIdx.x * blockDim.x + threadIdx.x) >> 5;
    int lane = threadIdx.x & 31;
    if (node >= N) return;
    const int start = rowptr[node];
    const int deg   = cnt[node];

    const float4* at4 = (const float4*)att;
    const int i4a = lane * 2;
    const float4 w0 = at4[i4a], w1 = at4[i4a + 1];
    float4 r0, r1;
    h8_to_f8(((const uint4*)(xrh + (size_t)node * 256))[lane], r0, r1);

    float den = 0.f;
    float4 acc0 = make_float4(0.f, 0.f, 0.f, 0.f);
    float4 acc1 = make_float4(0.f, 0.f, 0.f, 0.f);

    for (int i0 = 0; i0 < deg; i0 += 32) {
        int nn = min(32, deg - i0);
        int sReg = (lane < nn) ? csrsrc[start + i0 + lane] : 0;
        int i = 0;
        for (; i + 2 <= nn; i += 2) {
            int s0 = __shfl_sync(0xffffffffu, sReg, i);
            int s1 = __shfl_sync(0xffffffffu, sReg, i + 1);
            uint4 v0 = ((const uint4*)(xlh + (size_t)s0 * 256))[lane];
            uint4 v1 = ((const uint4*)(xlh + (size_t)s1 * 256))[lane];
            float4 A0, B0, A1, B1;
            h8_to_f8(v0, A0, B0);
            h8_to_f8(v1, A1, B1);
            float al0 = alpha_lane(A0, B0, r0, r1, w0, w1);
            float al1 = alpha_lane(A1, B1, r0, r1, w0, w1);
            #pragma unroll
            for (int o = 4; o; o >>= 1) {
                al0 += __shfl_xor_sync(0xffffffffu, al0, o);
                al1 += __shfl_xor_sync(0xffffffffu, al1, o);
            }
            float e0 = __expf(al0), e1 = __expf(al1);
            den += e0 + e1;
            acc0.x = fmaf(e0, A0.x, acc0.x); acc0.y = fmaf(e0, A0.y, acc0.y);
            acc0.z = fmaf(e0, A0.z, acc0.z); acc0.w = fmaf(e0, A0.w, acc0.w);
            acc1.x = fmaf(e0, B0.x, acc1.x); acc1.y = fmaf(e0, B0.y, acc1.y);
            acc1.z = fmaf(e0, B0.z, acc1.z); acc1.w = fmaf(e0, B0.w, acc1.w);
            acc0.x = fmaf(e1, A1.x, acc0.x); acc0.y = fmaf(e1, A1.y, acc0.y);
            acc0.z = fmaf(e1, A1.z, acc0.z); acc0.w = fmaf(e1, A1.w, acc0.w);
            acc1.x = fmaf(e1, B1.x, acc1.x); acc1.y = fmaf(e1, B1.y, acc1.y);
            acc1.z = fmaf(e1, B1.z, acc1.z); acc1.w = fmaf(e1, B1.w, acc1.w);
        }
        if (i < nn) {
            int sv = __shfl_sync(0xffffffffu, sReg, i);
            uint4 v = ((const uint4*)(xlh + (size_t)sv * 256))[lane];
            float4 A0, B0;
            h8_to_f8(v, A0, B0);
            float al = alpha_lane(A0, B0, r0, r1, w0, w1);
            #pragma unroll
            for (int o = 4; o; o >>= 1)
                al += __shfl_xor_sync(0xffffffffu, al, o);
            float ev = __expf(al);
            den += ev;
            acc0.x = fmaf(ev, A0.x, acc0.x); acc0.y = fmaf(ev, A0.y, acc0.y);
            acc0.z = fmaf(ev, A0.z, acc0.z); acc0.w = fmaf(ev, A0.w, acc0.w);
            acc1.x = fmaf(ev, B0.x, acc1.x); acc1.y = fmaf(ev, B0.y, acc1.y);
            acc1.z = fmaf(ev, B0.z, acc1.z); acc1.w = fmaf(ev, B0.w, acc1.w);
        }
    }

    const float inv = 0.25f / (den + 1e-16f);
    acc0.x *= inv; acc0.y *= inv; acc0.z *= inv; acc0.w *= inv;
    acc1.x *= inv; acc1.y *= inv; acc1.z *= inv; acc1.w *= inv;

    #pragma unroll
    for (int mask = 8; mask <= 16; mask <<= 1) {
        acc0.x += __shfl_xor_sync(0xffffffffu, acc0.x, mask);
        acc0.y += __shfl_xor_sync(0xffffffffu, acc0.y, mask);
        acc0.z += __shfl_xor_sync(0xffffffffu, acc0.z, mask);
        acc0.w += __shfl_xor_sync(0xffffffffu, acc0.w, mask);
        acc1.x += __shfl_xor_sync(0xffffffffu, acc1.x, mask);
        acc1.y += __shfl_xor_sync(0xffffffffu, acc1.y, mask);
        acc1.z += __shfl_xor_sync(0xffffffffu, acc1.z, mask);
        acc1.w += __shfl_xor_sync(0xffffffffu, acc1.w, mask);
    }

    if (!HEADS) {
        if (lane < 8) {
            const int c0 = lane * 8;
            float4 b0 = *(const float4*)(bias + c0);
            float4 b1 = *(const float4*)(bias + c0 + 4);
            float4 o0, o1;
            o0.x = eluf(acc0.x + b0.x);
            o0.y = eluf(acc0.y + b0.y);
            o0.z = eluf(acc0.z + b0.z);
            o0.w = eluf(acc0.w + b0.w);
            o1.x = eluf(acc1.x + b1.x);
            o1.y = eluf(acc1.y + b1.y);
            o1.z = eluf(acc1.z + b1.z);
            o1.w = eluf(acc1.w + b1.w);
            *(float4*)(out + (size_t)node * 64 + c0)     = o0;
            *(float4*)(out + (size_t)node * 64 + c0 + 4) = o1;
        }
    } else {
        const int warp = threadIdx.x >> 5;
        if (lane < 8) {
            const int c0 = lane * 8;
            float4 b0 = *(const float4*)(bias + c0);
            float4 b1 = *(const float4*)(bias + c0 + 4);
            float4 rr0 = *(const float4*)(resid + (size_t)node * 64 + c0);
            float4 rr1 = *(const float4*)(resid + (size_t)node * 64 + c0 + 4);
            float* s = sH2 + warp * 64 + c0;
            s[0] = eluf(acc0.x + b0.x + rr0.x);
            s[1] = eluf(acc0.y + b0.y + rr0.y);
            s[2] = eluf(acc0.z + b0.z + rr0.z);
            s[3] = eluf(acc0.w + b0.w + rr0.w);
            s[4] = eluf(acc1.x + b1.x + rr1.x);
            s[5] = eluf(acc1.y + b1.y + rr1.y);
            s[6] = eluf(acc1.z + b1.z + rr1.z);
            s[7] = eluf(acc1.w + b1.w + rr1.w);
        }
        __syncwarp();
        float amu = bmu[lane];
        float alv = blv[lane];
        const float* h2s = sH2 + warp * 64;
        #pragma unroll 16
        for (int c = 0; c < 64; c++) {
            float hv = h2s[c];
            amu = fmaf(hv, sW[c * 32 + lane], amu);
            alv = fmaf(hv, sW[2048 + c * 32 + lane], alv);
        }
        outmu[(size_t)node * 32 + lane] = amu;
        outlv[(size_t)node * 32 + lane] = alv;
        if (lane == 0) cnt[node] = 0;
    }
}

// ================= launch ========================================================
extern "C" void kernel_launch(void* const* d_in, const int* in_sizes, int n_in,
                              void* d_out, int out_size)
{
    const float* x    = (const float*)d_in[0];
    const int*   ei   = (const int*)  d_in[1];
    const float* W1   = (const float*)d_in[2];
    const float* b1   = (const float*)d_in[3];
    const float* lnw  = (const float*)d_in[4];
    const float* lnb  = (const float*)d_in[5];
    const float* Wl1  = (const float*)d_in[6];
    const float* bl1  = (const float*)d_in[7];
    const float* Wr1  = (const float*)d_in[8];
    const float* br1  = (const float*)d_in[9];
    const float* att1 = (const float*)d_in[10];
    const float* bias1= (const float*)d_in[11];
    const float* Wl2  = (const float*)d_in[12];
    const float* bl2  = (const float*)d_in[13];
    const float* Wr2  = (const float*)d_in[14];
    const float* br2  = (const float*)d_in[15];
    const float* att2 = (const float*)d_in[16];
    const float* bias2= (const float*)d_in[17];
    const float* Wmu  = (const float*)d_in[18];
    const float* bmu  = (const float*)d_in[19];
    const float* Wlv  = (const float*)d_in[20];
    const float* blv  = (const float*)d_in[21];
    float* out = (float*)d_out;

    const int N = in_sizes[0] / 128;
    const int E = in_sizes[1] / 2;
    const int* src = ei;
    const int* dst = ei + E;

    float *h, *h1;
    __half *xlh, *xrh;
    int *cnt, *rowptr, *woff, *part, *csrsrc;
    cudaGetSymbolAddress((void**)&h,      g_h);
    cudaGetSymbolAddress((void**)&xlh,    g_xlh);
    cudaGetSymbolAddress((void**)&xrh,    g_xrh);
    cudaGetSymbolAddress((void**)&h1,     g_h1);
    cudaGetSymbolAddress((void**)&cnt,    g_cnt);
    cudaGetSymbolAddress((void**)&rowptr, g_rowptr);
    cudaGetSymbolAddress((void**)&woff,   g_woff);
    cudaGetSymbolAddress((void**)&part,   g_part);
    cudaGetSymbolAddress((void**)&csrsrc, g_csrsrc);

    const int rb128 = (N + 127) / 128;
    const int NB    = (N + 255) / 256;
    const int quadB = (E + 1023) / 1024;       // 4 edges per thread
    const int quadT = quadB * 256;             // stride between chains
    const int scanY  = (NB + 3) / 4;
    const int nodeWarpGrid = (N + 7) / 8;

    // L1: stage-0 GEMM (+fused LN+ELU)  ∥  csr_count (4 edges/thread)
    fk_gemm0_count<<<dim3(1, rb128 + quadB), 256>>>(
        x, W1, b1, h, N, lnw, lnb, dst, cnt, E, quadT, rb128);

    // L2: layer-1 xl & xr GEMMs (fp16 out)  ∥  scan1
    fk_dualgemm_scan<<<dim3(4, rb128 + scanY), 256>>>(
        h, Wl1, bl1, Wr1, br1, xlh, xrh, N, 128,
        cnt, rowptr, part, N, NB, rb128);

    // L3-L4: finish CSR
    scan3f     <<<NB, 256>>>(rowptr, part, woff, N, NB);
    csr_scatter<<<quadB, 256>>>(src, dst, woff, csrsrc, E, quadT);

    // L5: GATv2 layer 1
    gat_node_t<false><<<nodeWarpGrid, 256>>>(
        xlh, xrh, rowptr, cnt, csrsrc, att1, bias1, nullptr, h1,
        nullptr, nullptr, nullptr, nullptr, nullptr, nullptr, N);

    // L6: layer-2 xl & xr GEMMs
    fk_dualgemm_scan<<<dim3(4, rb128), 256>>>(
        h1, Wl2, bl2, Wr2, br2, xlh, xrh, N, 64,
        cnt, rowptr, part, N, 0, rb128);

    // L7: GATv2 layer 2 + fused mu/lv heads + cnt self-zero
    gat_node_t<true><<<nodeWarpGrid, 256>>>(
        xlh, xrh, rowptr, cnt, csrsrc, att2, bias2, h1, nullptr,
        Wmu, bmu, Wlv, blv, out, out + (size_t)N * 32, N);
}

// round 17
// speedup vs baseline: 1.0208x; 1.0208x over previous
#include <cuda_runtime.h>
#include <cuda_fp16.h>
#include <math.h>
#include <stdint.h>

#define NMAX 50176
#define EMAX 800000

// ---------------- scratch (device globals; zero-initialized at module load) ----
__device__ float  g_h  [NMAX * 128];
__device__ __half g_xlh[NMAX * 256];
__device__ __half g_xrh[NMAX * 256];
__device__ __half g_h1h[NMAX * 64];
__device__ int    g_cnt   [NMAX];    // self-zeroed by gat layer-2 each run
__device__ int    g_rowptr[NMAX];
__device__ int    g_woff  [NMAX];
__device__ int    g_part  [256];
__device__ int    g_csrsrc[EMAX];

__device__ __forceinline__ float eluf(float x) { return x > 0.f ? x : expm1f(x); }

__device__ __forceinline__ void h8_to_f8(uint4 v, float4& A, float4& B)
{
    const __half2* hp = (const __half2*)&v;
    float2 f0 = __half22float2(hp[0]);
    float2 f1 = __half22float2(hp[1]);
    float2 f2 = __half22float2(hp[2]);
    float2 f3 = __half22float2(hp[3]);
    A = make_float4(f0.x, f0.y, f1.x, f1.y);
    B = make_float4(f2.x, f2.y, f3.x, f3.y);
}

// ================= GEMM body: 128x128 tile, BK=16, FFMA2 =======================
// AHALF: A operand is fp16 (row-major, K halves per row).
// Epilogue variants: fp32 store, fp16 store (Ch != nullptr), LN+ELU (lnw != nullptr).
template<bool AHALF>
__device__ __forceinline__ void gemm_body(
    const void* __restrict__ Av, const float* __restrict__ W,
    const float* __restrict__ bias, float* __restrict__ C, __half* __restrict__ Ch,
    int M, int K, int Nc, int rowBase, int colBase,
    const float* __restrict__ lnw, const float* __restrict__ lnb)
{
    __shared__ float As[2][16][128];
    __shared__ float Bs[2][16][128];

    const int tid = threadIdx.x;
    const int tx = tid & 15;
    const int ty = tid >> 4;

    const int lr = tid & 127;
    const int lc = (tid >> 7) * 4;      // 0 or 4
    const int wk = tid >> 5;
    const int wc = (tid & 31) * 4;

    const bool aok = (rowBase + lr) < M;
    const float*  ArowF = AHALF ? nullptr : (const float*)Av + (size_t)(rowBase + lr) * K;
    const __half* ArowH = AHALF ? (const __half*)Av + (size_t)(rowBase + lr) * K : nullptr;
    const float* Wp = W + colBase + wc;

    const float4 z4 = make_float4(0.f, 0.f, 0.f, 0.f);
    const uint4  zu = make_uint4(0u, 0u, 0u, 0u);
    float4 av0 = z4, av1 = z4;
    uint4  avh = zu;
    if (AHALF) { if (aok) avh = *(const uint4*)(ArowH + lc * 2); }
    else if (aok) {
        av0 = *(const float4*)(ArowF + lc);
        av1 = *(const float4*)(ArowF + lc + 8);
    }
    float4 bv0 = *(const float4*)(Wp + (size_t)wk * Nc);
    float4 bv1 = *(const float4*)(Wp + (size_t)(wk + 8) * Nc);

    if (AHALF) {
        float4 fa, fb; h8_to_f8(avh, fa, fb);
        const int cb = lc * 2;
        As[0][cb + 0][lr] = fa.x; As[0][cb + 1][lr] = fa.y;
        As[0][cb + 2][lr] = fa.z; As[0][cb + 3][lr] = fa.w;
        As[0][cb + 4][lr] = fb.x; As[0][cb + 5][lr] = fb.y;
        As[0][cb + 6][lr] = fb.z; As[0][cb + 7][lr] = fb.w;
    } else {
        As[0][lc + 0][lr] = av0.x; As[0][lc + 1][lr] = av0.y;
        As[0][lc + 2][lr] = av0.z; As[0][lc + 3][lr] = av0.w;
        As[0][lc + 8][lr] = av1.x; As[0][lc + 9][lr] = av1.y;
        As[0][lc +10][lr] = av1.z; As[0][lc +11][lr] = av1.w;
    }
    *(float4*)&Bs[0][wk][wc]     = bv0;
    *(float4*)&Bs[0][wk + 8][wc] = bv1;
    __syncthreads();

    unsigned long long acc2[8][4];
    #pragma unroll
    for (int i = 0; i < 8; i++)
        #pragma unroll
        for (int j = 0; j < 4; j++) acc2[i][j] = 0ULL;

    const int T = K >> 4;
    for (int t = 0; t < T; t++) {
        const int buf = t & 1;
        if (t + 1 < T) {
            const int k0 = (t + 1) << 4;
            if (AHALF) { avh = aok ? *(const uint4*)(ArowH + k0 + lc * 2) : zu; }
            else {
                av0 = aok ? *(const float4*)(ArowF + k0 + lc)     : z4;
                av1 = aok ? *(const float4*)(ArowF + k0 + lc + 8) : z4;
            }
            bv0 = *(const float4*)(Wp + (size_t)(k0 + wk) * Nc);
            bv1 = *(const float4*)(Wp + (size_t)(k0 + wk + 8) * Nc);
        }
        #pragma unroll
        for (int kk = 0; kk < 16; kk++) {
            float a[8];
            *(float4*)&a[0] = *(const float4*)&As[buf][kk][ty * 8];
            *(float4*)&a[4] = *(const float4*)&As[buf][kk][ty * 8 + 4];
            ulonglong2 q0 = *(const ulonglong2*)&Bs[buf][kk][tx * 8];
            ulonglong2 q1 = *(const ulonglong2*)&Bs[buf][kk][tx * 8 + 4];
            unsigned long long bp[4] = { q0.x, q0.y, q1.x, q1.y };
            #pragma unroll
            for (int i = 0; i < 8; i++) {
                unsigned long long ad;
                asm("mov.b64 %0, {%1,%1};" : "=l"(ad) : "f"(a[i]));
                #pragma unroll
                for (int j = 0; j < 4; j++)
                    asm("fma.rn.f32x2 %0, %1, %2, %0;"
                        : "+l"(acc2[i][j]) : "l"(ad), "l"(bp[j]));
            }
        }
        if (t + 1 < T) {
            const int nb = buf ^ 1;
            if (AHALF) {
                float4 fa, fb; h8_to_f8(avh, fa, fb);
                const int cb = lc * 2;
                As[nb][cb + 0][lr] = fa.x; As[nb][cb + 1][lr] = fa.y;
                As[nb][cb + 2][lr] = fa.z; As[nb][cb + 3][lr] = fa.w;
                As[nb][cb + 4][lr] = fb.x; As[nb][cb + 5][lr] = fb.y;
                As[nb][cb + 6][lr] = fb.z; As[nb][cb + 7][lr] = fb.w;
            } else {
                As[nb][lc + 0][lr] = av0.x; As[nb][lc + 1][lr] = av0.y;
                As[nb][lc + 2][lr] = av0.z; As[nb][lc + 3][lr] = av0.w;
                As[nb][lc + 8][lr] = av1.x; As[nb][lc + 9][lr] = av1.y;
                As[nb][lc +10][lr] = av1.z; As[nb][lc +11][lr] = av1.w;
            }
            *(float4*)&Bs[nb][wk][wc]     = bv0;
            *(float4*)&Bs[nb][wk + 8][wc] = bv1;
            __syncthreads();
        }
    }

    const int cbase = colBase + tx * 8;
    float4 b0 = *(const float4*)(bias + cbase);
    float4 b1 = *(const float4*)(bias + cbase + 4);

    if (Ch != nullptr) {
        #pragma unroll
        for (int i = 0; i < 8; i++) {
            int r = rowBase + ty * 8 + i;
            if (r >= M) continue;
            float c[8];
            #pragma unroll
            for (int j = 0; j < 4; j++)
                asm("mov.b64 {%0,%1}, %2;" : "=f"(c[2*j]), "=f"(c[2*j+1]) : "l"(acc2[i][j]));
            __half2 hh[4];
            hh[0] = __floats2half2_rn(c[0] + b0.x, c[1] + b0.y);
            hh[1] = __floats2half2_rn(c[2] + b0.z, c[3] + b0.w);
            hh[2] = __floats2half2_rn(c[4] + b1.x, c[5] + b1.y);
            hh[3] = __floats2half2_rn(c[6] + b1.z, c[7] + b1.w);
            *(uint4*)(Ch + (size_t)r * Nc + cbase) = *(uint4*)hh;
        }
    } else if (lnw == nullptr) {
        #pragma unroll
        for (int i = 0; i < 8; i++) {
            int r = rowBase + ty * 8 + i;
            if (r >= M) continue;
            float c[8];
            #pragma unroll
            for (int j = 0; j < 4; j++)
                asm("mov.b64 {%0,%1}, %2;" : "=f"(c[2*j]), "=f"(c[2*j+1]) : "l"(acc2[i][j]));
            float4 o0 = make_float4(c[0] + b0.x, c[1] + b0.y, c[2] + b0.z, c[3] + b0.w);
            float4 o1 = make_float4(c[4] + b1.x, c[5] + b1.y, c[6] + b1.z, c[7] + b1.w);
            *(float4*)(C + (size_t)r * Nc + cbase)     = o0;
            *(float4*)(C + (size_t)r * Nc + cbase + 4) = o1;
        }
    } else {
        float s[8], sq[8];
        #pragma unroll
        for (int i = 0; i < 8; i++) {
            float c[8];
            #pragma unroll
            for (int j = 0; j < 4; j++)
                asm("mov.b64 {%0,%1}, %2;" : "=f"(c[2*j]), "=f"(c[2*j+1]) : "l"(acc2[i][j]));
            c[0] += b0.x; c[1] += b0.y; c[2] += b0.z; c[3] += b0.w;
            c[4] += b1.x; c[5] += b1.y; c[6] += b1.z; c[7] += b1.w;
            float ss = 0.f, qq = 0.f;
            #pragma unroll
            for (int j = 0; j < 8; j++) { ss += c[j]; qq += c[j] * c[j]; }
            s[i] = ss; sq[i] = qq;
        }
        #pragma unroll
        for (int o = 1; o < 16; o <<= 1) {
            #pragma unroll
            for (int i = 0; i < 8; i++) {
                s[i]  += __shfl_xor_sync(0xffffffffu, s[i],  o);
                sq[i] += __shfl_xor_sync(0xffffffffu, sq[i], o);
            }
        }
        float4 lw0 = *(const float4*)(lnw + cbase);
        float4 lw1 = *(const float4*)(lnw + cbase + 4);
        float4 lb0 = *(const float4*)(lnb + cbase);
        float4 lb1 = *(const float4*)(lnb + cbase + 4);
        #pragma unroll
        for (int i = 0; i < 8; i++) {
            int r = rowBase + ty * 8 + i;
            if (r >= M) continue;
            float mean = s[i] * (1.f / 128.f);
            float var  = sq[i] * (1.f / 128.f) - mean * mean;
            float inv  = rsqrtf(var + 1e-5f);
            float c[8];
            #pragma unroll
            for (int j = 0; j < 4; j++)
                asm("mov.b64 {%0,%1}, %2;" : "=f"(c[2*j]), "=f"(c[2*j+1]) : "l"(acc2[i][j]));
            c[0] += b0.x; c[1] += b0.y; c[2] += b0.z; c[3] += b0.w;
            c[4] += b1.x; c[5] += b1.y; c[6] += b1.z; c[7] += b1.w;
            float4 o0, o1;
            o0.x = eluf((c[0] - mean) * inv * lw0.x + lb0.x);
            o0.y = eluf((c[1] - mean) * inv * lw0.y + lb0.y);
            o0.z = eluf((c[2] - mean) * inv * lw0.z + lb0.z);
            o0.w = eluf((c[3] - mean) * inv * lw0.w + lb0.w);
            o1.x = eluf((c[4] - mean) * inv * lw1.x + lb1.x);
            o1.y = eluf((c[5] - mean) * inv * lw1.y + lb1.y);
            o1.z = eluf((c[6] - mean) * inv * lw1.z + lb1.z);
            o1.w = eluf((c[7] - mean) * inv * lw1.w + lb1.w);
            *(float4*)(C + (size_t)r * Nc + cbase)     = o0;
            *(float4*)(C + (size_t)r * Nc + cbase + 4) = o1;
        }
    }
}

// ================= CSR small kernels =============================================
__device__ __forceinline__ void scan1_body(const int* __restrict__ cnt,
                                           int* __restrict__ rowptr,
                                           int* __restrict__ part, int N, int b)
{
    __shared__ int sh[256];
    int tid = threadIdx.x;
    int i = b * 256 + tid;
    int v = (i < N) ? cnt[i] : 0;
    sh[tid] = v; __syncthreads();
    #pragma unroll
    for (int o = 1; o < 256; o <<= 1) {
        int t = (tid >= o) ? sh[tid - o] : 0;
        __syncthreads();
        sh[tid] += t;
        __syncthreads();
    }
    if (i < N) rowptr[i] = sh[tid] - v;
    if (tid == 255) part[b] = sh[255];
}
__global__ void scan3f(int* __restrict__ rowptr, const int* __restrict__ part,
                       int* __restrict__ woff, int N, int NB)
{
    __shared__ int sh[256];
    int tid = threadIdx.x;
    int v = (tid < NB) ? part[tid] : 0;
    sh[tid] = v; __syncthreads();
    #pragma unroll
    for (int o = 1; o < 256; o <<= 1) {
        int t = (tid >= o) ? sh[tid - o] : 0;
        __syncthreads();
        sh[tid] += t;
        __syncthreads();
    }
    int i = blockIdx.x * 256 + tid;
    if (i < N) {
        int b = blockIdx.x;
        int off = sh[b] - ((b < NB) ? part[b] : 0);
        int r = rowptr[i] + off;
        rowptr[i] = r;
        woff[i] = r;
    }
}
__global__ void csr_scatter(const int* __restrict__ src, const int* __restrict__ dst,
                            int* __restrict__ woff, int* __restrict__ csrsrc, int E)
{
    int e = blockIdx.x * blockDim.x + threadIdx.x;
    if (e < E) {
        int p = atomicAdd(&woff[dst[e]], 1);
        csrsrc[p] = src[e];
    }
}

// ================= FAT kernel 1: stage-0 GEMM (+LN+ELU)  ∥  csr_count ===========
__global__ void __launch_bounds__(256, 2)
fk_gemm0_count(const float* __restrict__ x, const float* __restrict__ W1,
               const float* __restrict__ b1, float* __restrict__ h, int M,
               const float* __restrict__ lnw, const float* __restrict__ lnb,
               const int* __restrict__ dst, int* __restrict__ cnt, int E, int rbY)
{
    if ((int)blockIdx.y < rbY) {
        gemm_body<false>(x, W1, b1, h, nullptr, M, 128, 128, blockIdx.y * 128, 0,
                         lnw, lnb);
    } else {
        int i = (blockIdx.y - rbY) * 256 + threadIdx.x;
        if (i < E) atomicAdd(&cnt[dst[i]], 1);
    }
}

// ================= FAT kernel 2: dual GEMM (fp16 out)  ∥  optional scan1 ========
template<bool AHALF>
__global__ void __launch_bounds__(256, 2)
fk_dualgemm_scan(const void* __restrict__ A,
                 const float* __restrict__ Wl, const float* __restrict__ bl,
                 const float* __restrict__ Wr, const float* __restrict__ br,
                 __half* __restrict__ Clh, __half* __restrict__ Crh, int M, int K,
                 const int* __restrict__ cnt, int* __restrict__ rowptr,
                 int* __restrict__ part, int N, int NB, int rbY)
{
    if ((int)blockIdx.y < rbY) {
        const int which = blockIdx.x >> 1;
        const int colBase = (blockIdx.x & 1) * 128;
        gemm_body<AHALF>(A, which ? Wr : Wl, which ? br : bl, nullptr,
                         which ? Crh : Clh, M, K, 256, blockIdx.y * 128, colBase,
                         nullptr, nullptr);
    } else {
        int b = (blockIdx.y - rbY) * 4 + blockIdx.x;
        if (b < NB) scan1_body(cnt, rowptr, part, N, b);
    }
}

// ================= fused node-major GATv2 (2-way ILP, fp16 everywhere) =========
__device__ __forceinline__ float alpha_lane(const float4 a0, const float4 a1,
                                            const float4 r0, const float4 r1,
                                            const float4 w0, const float4 w1)
{
    float t, al = 0.f;
    t = a0.x + r0.x; t = t >= 0.f ? t : 0.2f * t; al += t * w0.x;
    t = a0.y + r0.y; t = t >= 0.f ? t : 0.2f * t; al += t * w0.y;
    t = a0.z + r0.z; t = t >= 0.f ? t : 0.2f * t; al += t * w0.z;
    t = a0.w + r0.w; t = t >= 0.f ? t : 0.2f * t; al += t * w0.w;
    t = a1.x + r1.x; t = t >= 0.f ? t : 0.2f * t; al += t * w1.x;
    t = a1.y + r1.y; t = t >= 0.f ? t : 0.2f * t; al += t * w1.y;
    t = a1.z + r1.z; t = t >= 0.f ? t : 0.2f * t; al += t * w1.z;
    t = a1.w + r1.w; t = t >= 0.f ? t : 0.2f * t; al += t * w1.w;
    return al;
}

template<bool HEADS>
__global__ void gat_node_t(const __half* __restrict__ xlh, const __half* __restrict__ xrh,
                           const int* __restrict__ rowptr, int* __restrict__ cnt,
                           const int* __restrict__ csrsrc, const float* __restrict__ att,
                           const float* __restrict__ bias,
                           const __half* __restrict__ residh, __half* __restrict__ outh,
                           const float* __restrict__ Wmu, const float* __restrict__ bmu,
                           const float* __restrict__ Wlv, const float* __restrict__ blv,
                           float* __restrict__ outmu, float* __restrict__ outlv, int N)
{
    __shared__ float sW [HEADS ? 4096 : 1];
    __shared__ float sH2[HEADS ? 512  : 1];

    if (HEADS) {
        for (int i = threadIdx.x; i < 4096; i += blockDim.x)
            sW[i] = (i < 2048) ? Wmu[i] : Wlv[i - 2048];
        __syncthreads();
    }

    int node = (blockIdx.x * blockDim.x + threadIdx.x) >> 5;
    int lane = threadIdx.x & 31;
    if (node >= N) return;
    const int start = rowptr[node];
    const int deg   = cnt[node];

    const float4* at4 = (const float4*)att;
    const int i4a = lane * 2;
    const float4 w0 = at4[i4a], w1 = at4[i4a + 1];
    float4 r0, r1;
    h8_to_f8(((const uint4*)(xrh + (size_t)node * 256))[lane], r0, r1);

    float den = 0.f;
    float4 acc0 = make_float4(0.f, 0.f, 0.f, 0.f);
    float4 acc1 = make_float4(0.f, 0.f, 0.f, 0.f);

    for (int i0 = 0; i0 < deg; i0 += 32) {
        int nn = min(32, deg - i0);
        int sReg = (lane < nn) ? csrsrc[start + i0 + lane] : 0;
        int i = 0;
        for (; i + 2 <= nn; i += 2) {
            int s0 = __shfl_sync(0xffffffffu, sReg, i);
            int s1 = __shfl_sync(0xffffffffu, sReg, i + 1);
            uint4 v0 = ((const uint4*)(xlh + (size_t)s0 * 256))[lane];
            uint4 v1 = ((const uint4*)(xlh + (size_t)s1 * 256))[lane];
            float4 A0, B0, A1, B1;
            h8_to_f8(v0, A0, B0);
            h8_to_f8(v1, A1, B1);
            float al0 = alpha_lane(A0, B0, r0, r1, w0, w1);
            float al1 = alpha_lane(A1, B1, r0, r1, w0, w1);
            #pragma unroll
            for (int o = 4; o; o >>= 1) {
                al0 += __shfl_xor_sync(0xffffffffu, al0, o);
                al1 += __shfl_xor_sync(0xffffffffu, al1, o);
            }
            float e0 = __expf(al0), e1 = __expf(al1);
            den += e0 + e1;
            acc0.x = fmaf(e0, A0.x, acc0.x); acc0.y = fmaf(e0, A0.y, acc0.y);
            acc0.z = fmaf(e0, A0.z, acc0.z); acc0.w = fmaf(e0, A0.w, acc0.w);
            acc1.x = fmaf(e0, B0.x, acc1.x); acc1.y = fmaf(e0, B0.y, acc1.y);
            acc1.z = fmaf(e0, B0.z, acc1.z); acc1.w = fmaf(e0, B0.w, acc1.w);
            acc0.x = fmaf(e1, A1.x, acc0.x); acc0.y = fmaf(e1, A1.y, acc0.y);
            acc0.z = fmaf(e1, A1.z, acc0.z); acc0.w = fmaf(e1, A1.w, acc0.w);
            acc1.x = fmaf(e1, B1.x, acc1.x); acc1.y = fmaf(e1, B1.y, acc1.y);
            acc1.z = fmaf(e1, B1.z, acc1.z); acc1.w = fmaf(e1, B1.w, acc1.w);
        }
        if (i < nn) {
            int sv = __shfl_sync(0xffffffffu, sReg, i);
            uint4 v = ((const uint4*)(xlh + (size_t)sv * 256))[lane];
            float4 A0, B0;
            h8_to_f8(v, A0, B0);
            float al = alpha_lane(A0, B0, r0, r1, w0, w1);
            #pragma unroll
            for (int o = 4; o; o >>= 1)
                al += __shfl_xor_sync(0xffffffffu, al, o);
            float ev = __expf(al);
            den += ev;
            acc0.x = fmaf(ev, A0.x, acc0.x); acc0.y = fmaf(ev, A0.y, acc0.y);
            acc0.z = fmaf(ev, A0.z, acc0.z); acc0.w = fmaf(ev, A0.w, acc0.w);
            acc1.x = fmaf(ev, B0.x, acc1.x); acc1.y = fmaf(ev, B0.y, acc1.y);
            acc1.z = fmaf(ev, B0.z, acc1.z); acc1.w = fmaf(ev, B0.w, acc1.w);
        }
    }

    const float inv = 0.25f / (den + 1e-16f);
    acc0.x *= inv; acc0.y *= inv; acc0.z *= inv; acc0.w *= inv;
    acc1.x *= inv; acc1.y *= inv; acc1.z *= inv; acc1.w *= inv;

    #pragma unroll
    for (int mask = 8; mask <= 16; mask <<= 1) {
        acc0.x += __shfl_xor_sync(0xffffffffu, acc0.x, mask);
        acc0.y += __shfl_xor_sync(0xffffffffu, acc0.y, mask);
        acc0.z += __shfl_xor_sync(0xffffffffu, acc0.z, mask);
        acc0.w += __shfl_xor_sync(0xffffffffu, acc0.w, mask);
        acc1.x += __shfl_xor_sync(0xffffffffu, acc1.x, mask);
        acc1.y += __shfl_xor_sync(0xffffffffu, acc1.y, mask);
        acc1.z += __shfl_xor_sync(0xffffffffu, acc1.z, mask);
        acc1.w += __shfl_xor_sync(0xffffffffu, acc1.w, mask);
    }

    if (!HEADS) {
        if (lane < 8) {
            const int c0 = lane * 8;
            float4 b0 = *(const float4*)(bias + c0);
            float4 b1 = *(const float4*)(bias + c0 + 4);
            __half2 hh[4];
            hh[0] = __floats2half2_rn(eluf(acc0.x + b0.x), eluf(acc0.y + b0.y));
            hh[1] = __floats2half2_rn(eluf(acc0.z + b0.z), eluf(acc0.w + b0.w));
            hh[2] = __floats2half2_rn(eluf(acc1.x + b1.x), eluf(acc1.y + b1.y));
            hh[3] = __floats2half2_rn(eluf(acc1.z + b1.z), eluf(acc1.w + b1.w));
            *(uint4*)(outh + (size_t)node * 64 + c0) = *(uint4*)hh;
        }
    } else {
        const int warp = threadIdx.x >> 5;
        if (lane < 8) {
            const int c0 = lane * 8;
            float4 b0 = *(const float4*)(bias + c0);
            float4 b1 = *(const float4*)(bias + c0 + 4);
            float4 rr0, rr1;
            h8_to_f8(*(const uint4*)(residh + (size_t)node * 64 + c0), rr0, rr1);
            float* s = sH2 + warp * 64 + c0;
            s[0] = eluf(acc0.x + b0.x + rr0.x);
            s[1] = eluf(acc0.y + b0.y + rr0.y);
            s[2] = eluf(acc0.z + b0.z + rr0.z);
            s[3] = eluf(acc0.w + b0.w + rr0.w);
            s[4] = eluf(acc1.x + b1.x + rr1.x);
            s[5] = eluf(acc1.y + b1.y + rr1.y);
            s[6] = eluf(acc1.z + b1.z + rr1.z);
            s[7] = eluf(acc1.w + b1.w + rr1.w);
        }
        __syncwarp();
        float amu = bmu[lane];
        float alv = blv[lane];
        const float* h2s = sH2 + warp * 64;
        #pragma unroll 16
        for (int c = 0; c < 64; c++) {
            float hv = h2s[c];
            amu = fmaf(hv, sW[c * 32 + lane], amu);
            alv = fmaf(hv, sW[2048 + c * 32 + lane], alv);
        }
        outmu[(size_t)node * 32 + lane] = amu;
        outlv[(size_t)node * 32 + lane] = alv;
        if (lane == 0) cnt[node] = 0;
    }
}

// ================= launch ========================================================
extern "C" void kernel_launch(void* const* d_in, const int* in_sizes, int n_in,
                              void* d_out, int out_size)
{
    const float* x    = (const float*)d_in[0];
    const int*   ei   = (const int*)  d_in[1];
    const float* W1   = (const float*)d_in[2];
    const float* b1   = (const float*)d_in[3];
    const float* lnw  = (const float*)d_in[4];
    const float* lnb  = (const float*)d_in[5];
    const float* Wl1  = (const float*)d_in[6];
    const float* bl1  = (const float*)d_in[7];
    const float* Wr1  = (const float*)d_in[8];
    const float* br1  = (const float*)d_in[9];
    const float* att1 = (const float*)d_in[10];
    const float* bias1= (const float*)d_in[11];
    const float* Wl2  = (const float*)d_in[12];
    const float* bl2  = (const float*)d_in[13];
    const float* Wr2  = (const float*)d_in[14];
    const float* br2  = (const float*)d_in[15];
    const float* att2 = (const float*)d_in[16];
    const float* bias2= (const float*)d_in[17];
    const float* Wmu  = (const float*)d_in[18];
    const float* bmu  = (const float*)d_in[19];
    const float* Wlv  = (const float*)d_in[20];
    const float* blv  = (const float*)d_in[21];
    float* out = (float*)d_out;

    const int N = in_sizes[0] / 128;
    const int E = in_sizes[1] / 2;
    const int* src = ei;
    const int* dst = ei + E;

    float *h;
    __half *xlh, *xrh, *h1h;
    int *cnt, *rowptr, *woff, *part, *csrsrc;
    cudaGetSymbolAddress((void**)&h,      g_h);
    cudaGetSymbolAddress((void**)&xlh,    g_xlh);
    cudaGetSymbolAddress((void**)&xrh,    g_xrh);
    cudaGetSymbolAddress((void**)&h1h,    g_h1h);
    cudaGetSymbolAddress((void**)&cnt,    g_cnt);
    cudaGetSymbolAddress((void**)&rowptr, g_rowptr);
    cudaGetSymbolAddress((void**)&woff,   g_woff);
    cudaGetSymbolAddress((void**)&part,   g_part);
    cudaGetSymbolAddress((void**)&csrsrc, g_csrsrc);

    const int rb128 = (N + 127) / 128;
    const int NB    = (N + 255) / 256;
    const int countB = (E + 255) / 256;
    const int scanY  = (NB + 3) / 4;
    const int nodeWarpGrid = (N + 7) / 8;

    // L1: stage-0 GEMM (+fused LN+ELU)  ∥  csr_count
    fk_gemm0_count<<<dim3(1, rb128 + countB), 256>>>(
        x, W1, b1, h, N, lnw, lnb, dst, cnt, E, rb128);

    // L2: layer-1 xl & xr GEMMs (fp16 out)  ∥  scan1
    fk_dualgemm_scan<false><<<dim3(4, rb128 + scanY), 256>>>(
        h, Wl1, bl1, Wr1, br1, xlh, xrh, N, 128,
        cnt, rowptr, part, N, NB, rb128);

    // L3-L4: finish CSR
    scan3f     <<<NB, 256>>>(rowptr, part, woff, N, NB);
    csr_scatter<<<countB, 256>>>(src, dst, woff, csrsrc, E);

    // L5: GATv2 layer 1 (h1 in fp16)
    gat_node_t<false><<<nodeWarpGrid, 256>>>(
        xlh, xrh, rowptr, cnt, csrsrc, att1, bias1, nullptr, h1h,
        nullptr, nullptr, nullptr, nullptr, nullptr, nullptr, N);

    // L6: layer-2 xl & xr GEMMs (fp16 A)
    fk_dualgemm_scan<true><<<dim3(4, rb128), 256>>>(
        h1h, Wl2, bl2, Wr2, br2, xlh, xrh, N, 64,
        cnt, rowptr, part, N, 0, rb128);

    // L7: GATv2 layer 2 + fused mu/lv heads + cnt self-zero
    gat_node_t<true><<<nodeWarpGrid, 256>>>(
        xlh, xrh, rowptr, cnt, csrsrc, att2, bias2, h1h, nullptr,
        Wmu, bmu, Wlv, blv, out, out + (size_t)N * 32, N);
}